// round 8
// baseline (speedup 1.0000x reference)
#include <cuda_runtime.h>
#include <cstdint>

// BsplineEncoding: x[1e6,3] -> out[1e6,195]. Per (point,dim): [x, 64 bins],
// only 4 bins nonzero; all 195M floats must be written.
//
// R5 (115.2us, DRAM 81.7%): per-block tiles, full re-zero, exit wait.
// R7: persistent double-buffered CTAs.
//  - zero both buffers ONCE; thereafter each worker clears only its previous
//    4 bins before scattering the new 4 (tile contents are 99% identical
//    zeros between iterations of the same buffer).
//  - one bulk-async store per tile, wait_group 1 before buffer reuse ->
//    TMA continuously fed, one exit-wait per CTA instead of per tile.

static constexpr float SCALE    = 30.5f;            // (K-DEG)/(MAX-MIN)
static constexpr float CLAMP_HI = 61.0f - 1e-6f;    // K - DEG - EPS
static constexpr int   PTS   = 32;
static constexpr int   TFLOATS = PTS * 195;         // 6240
static constexpr int   TBYTES  = TFLOATS * 4;       // 24960 (16B multiple)
static constexpr int   TVEC4   = TFLOATS / 4;       // 1560
static constexpr int   THREADS = 256;
static constexpr int   NWORK   = PTS * 3;           // 96 workers

__device__ __forceinline__ uint32_t smem_u32(const void* p) {
    uint32_t a;
    asm("{ .reg .u64 t; cvta.to.shared.u64 t, %1; cvt.u32.u64 %0, t; }"
        : "=r"(a) : "l"(p));
    return a;
}

__global__ __launch_bounds__(THREADS)
void bspline_enc_kernel(const float* __restrict__ xin,
                        float* __restrict__ out,
                        int n_tiles)
{
    __shared__ __align__(16) float tile[2][TFLOATS];
    const int tid = threadIdx.x;

    // One-time zero of both buffers.
    float4 z4 = make_float4(0.f, 0.f, 0.f, 0.f);
    float4* t4 = reinterpret_cast<float4*>(tile);
#pragma unroll 4
    for (int i = tid; i < 2 * TVEC4; i += THREADS)
        t4[i] = z4;
    __syncthreads();

    const int p = tid / 3;              // local point (workers only)
    const int d = tid - p * 3;          // dim
    int prev_idx[2] = {-1, -1};         // per-buffer previous scatter base

    int it = 0;
    for (int t = blockIdx.x; t < n_tiles; t += gridDim.x, ++it) {
        const int buf = it & 1;

        // Ensure the bulk read that last consumed this buffer (committed at
        // iteration it-2) is complete: allow only 1 outstanding group.
        if (tid == 0)
            asm volatile("cp.async.bulk.wait_group 1;" ::: "memory");
        __syncthreads();

        if (tid < NWORK) {
            const float xv = __ldg(xin + (size_t)t * NWORK + tid);

            float xs = fminf(fmaxf((xv + 1.0f) * SCALE, 0.0f), CLAMP_HI);
            float fi = floorf(xs);
            int  idx = (int)fi;
            float u  = xs - fi;
            float u2 = u * u;
            float u3 = u2 * u;
            float om = 1.0f - u;
            float c0 = om * om * om * (1.0f / 6.0f);
            float c1 = (3.0f * u3 - 6.0f * u2 + 4.0f) * (1.0f / 6.0f);
            float c2 = (-3.0f * u3 + 3.0f * u2 + 3.0f * u + 1.0f) * (1.0f / 6.0f);
            float c3 = u3 * (1.0f / 6.0f);

            float* dst = tile[buf] + p * 195 + d * 65;
            int pi = prev_idx[buf];
            if (pi >= 0 && pi != idx) {      // clear stale bins from 2 iters ago
                dst[1 + pi] = 0.f;
                dst[2 + pi] = 0.f;
                dst[3 + pi] = 0.f;
                dst[4 + pi] = 0.f;
            }
            dst[0]       = xv;
            dst[1 + idx] = c0;
            dst[2 + idx] = c1;
            dst[3 + idx] = c2;
            dst[4 + idx] = c3;
            prev_idx[buf] = idx;
        }
        __syncthreads();

        if (tid == 0) {
            asm volatile("fence.proxy.async.shared::cta;" ::: "memory");
            float* gdst = out + (size_t)t * TFLOATS;
            uint32_t src = smem_u32(tile[buf]);
            asm volatile(
                "cp.async.bulk.global.shared::cta.bulk_group [%0], [%1], %2;"
                :: "l"(gdst), "r"(src), "n"(TBYTES) : "memory");
            asm volatile("cp.async.bulk.commit_group;" ::: "memory");
        }
    }

    // smem dies at exit; all bulk reads must finish first.
    if (tid == 0)
        asm volatile("cp.async.bulk.wait_group 0;" ::: "memory");
}

extern "C" void kernel_launch(void* const* d_in, const int* in_sizes, int n_in,
                              void* d_out, int out_size)
{
    const float* x = (const float*)d_in[0];
    float* out = (float*)d_out;

    int n_points = out_size / 195;
    int n_tiles  = n_points / PTS;           // 31250 for N = 1e6
    int blocks   = 592;                      // 4 CTAs/SM x 148 SMs
    if (blocks > n_tiles) blocks = n_tiles;
    bspline_enc_kernel<<<blocks, THREADS>>>(x, out, n_tiles);
}

// round 9
// speedup vs baseline: 1.1347x; 1.1347x over previous
#include <cuda_runtime.h>
#include <cstdint>

// BsplineEncoding: x[1e6,3] -> out[1e6,195]. Per (point,dim): [x, 64 bins],
// only 4 bins nonzero; all 195M floats must be written.
//
// History: R1 direct per-element = issue-bound (445us). R3 smem staging =
// 117us, DRAM 79%. R4 TMA drain = neutral (path-independent BW cap). R5
// 64-pt tiles = 115.2us, DRAM 81.7%. R7 persistent CTAs = REGRESSION
// (137us) — lost inter-block overlap.
//
// R8: R5 structure, but STG drain (no exit wait -> blocks retire at store
// issue, deep block pipeline restored) and 512 threads (faster drain).

static constexpr float SCALE    = 30.5f;            // (K-DEG)/(MAX-MIN) = 61/2
static constexpr float CLAMP_HI = 61.0f - 1e-6f;    // K - DEG - EPS
static constexpr int   PTS_PER_BLK = 64;
static constexpr int   TILE_FLOATS = PTS_PER_BLK * 195;   // 12480
static constexpr int   TILE_VEC4   = TILE_FLOATS / 4;     // 3120
static constexpr int   THREADS     = 512;
static constexpr int   NWORK       = PTS_PER_BLK * 3;     // 192 workers

__global__ __launch_bounds__(THREADS)
void bspline_enc_kernel(const float* __restrict__ xin,
                        float* __restrict__ out)
{
    __shared__ __align__(16) float tile[TILE_FLOATS];
    const int tid = threadIdx.x;

    // Phase 1: zero the tile (float4 stores, conflict-free).
    float4 z4 = make_float4(0.f, 0.f, 0.f, 0.f);
    float4* t4 = reinterpret_cast<float4*>(tile);
#pragma unroll
    for (int i = tid; i < TILE_VEC4; i += THREADS)
        t4[i] = z4;
    __syncthreads();

    // Phase 2: 192 workers, one per (point, dim). Coalesced input load.
    if (tid < NWORK) {
        const int p = tid / 3;
        const int d = tid - p * 3;
        const float xv = __ldg(xin + (size_t)blockIdx.x * NWORK + tid);

        float xs = fminf(fmaxf((xv + 1.0f) * SCALE, 0.0f), CLAMP_HI);
        float fi = floorf(xs);
        int  idx = (int)fi;
        float u  = xs - fi;
        float u2 = u * u;
        float u3 = u2 * u;
        float om = 1.0f - u;
        float c0 = om * om * om * (1.0f / 6.0f);
        float c1 = (3.0f * u3 - 6.0f * u2 + 4.0f) * (1.0f / 6.0f);
        float c2 = (-3.0f * u3 + 3.0f * u2 + 3.0f * u + 1.0f) * (1.0f / 6.0f);
        float c3 = u3 * (1.0f / 6.0f);

        float* dst = tile + p * 195 + d * 65;
        dst[0]       = xv;
        dst[1 + idx] = c0;
        dst[2 + idx] = c1;
        dst[3 + idx] = c2;
        dst[4 + idx] = c3;
    }
    __syncthreads();

    // Phase 3: coalesced float4 stream to global. Fire-and-forget: the block
    // retires as soon as stores issue, keeping the block pipeline deep.
    float4* o4 = reinterpret_cast<float4*>(out) + (size_t)blockIdx.x * TILE_VEC4;
#pragma unroll
    for (int i = tid; i < TILE_VEC4; i += THREADS)
        o4[i] = t4[i];
}

extern "C" void kernel_launch(void* const* d_in, const int* in_sizes, int n_in,
                              void* d_out, int out_size)
{
    const float* x = (const float*)d_in[0];
    float* out = (float*)d_out;

    int n_points = out_size / 195;
    int blocks   = n_points / PTS_PER_BLK;   // 15625 for N = 1e6
    bspline_enc_kernel<<<blocks, THREADS>>>(x, out);
}

// round 10
// speedup vs baseline: 1.1751x; 1.0356x over previous
#include <cuda_runtime.h>
#include <cstdint>

// BsplineEncoding: x[1e6,3] -> out[1e6,195]. Per (point,dim): [x, 64 bins],
// only 4 bins nonzero; all 195M floats must be written => pure write stream,
// 780 MB, empirically capped at ~6.9 TB/s on this chip.
//
// Round history:
//  R1 per-output-element compute: 445us (issue-bound).
//  R3 32pt smem tile + STG drain: 117.4us, DRAM 79.2%.
//  R4 TMA drain: neutral (BW path-independent).
//  R5 64pt tile + dual TMA store + exit wait: 115.2us, DRAM 81.7%  <-- best
//  R7 persistent double-buffered CTAs: 137us REGRESSION (lost overlap).
//  R8 STG drain + 512thr: 120.9us REGRESSION (TMA drain + 256thr wins).
//
// R9 = R5 + (a) input LDG hoisted above the zero phase to hide its latency,
// (b) four quarter-size bulk stores for deeper TMA request interleave.

static constexpr float SCALE    = 30.5f;            // (K-DEG)/(MAX-MIN) = 61/2
static constexpr float CLAMP_HI = 61.0f - 1e-6f;    // K - DEG - EPS
static constexpr int   PTS_PER_BLK = 64;
static constexpr int   TILE_FLOATS = PTS_PER_BLK * 195;   // 12480
static constexpr int   TILE_BYTES  = TILE_FLOATS * 4;     // 49920
static constexpr int   QTR_BYTES   = TILE_BYTES / 4;      // 12480 (16B mult)
static constexpr int   QTR_FLOATS  = TILE_FLOATS / 4;     // 3120
static constexpr int   TILE_VEC4   = TILE_FLOATS / 4;     // 3120
static constexpr int   THREADS     = 256;
static constexpr int   NWORK       = PTS_PER_BLK * 3;     // 192 workers

__device__ __forceinline__ uint32_t smem_u32(const void* p) {
    uint32_t a;
    asm("{ .reg .u64 t; cvta.to.shared.u64 t, %1; cvt.u32.u64 %0, t; }"
        : "=r"(a) : "l"(p));
    return a;
}

__global__ __launch_bounds__(THREADS)
void bspline_enc_kernel(const float* __restrict__ xin,
                        float* __restrict__ out)
{
    __shared__ __align__(16) float tile[TILE_FLOATS];
    const int tid = threadIdx.x;

    // Hoisted input load: LDG issues before the zero phase; its latency is
    // hidden under the ~12 STS.128 iterations below.
    float xv = 0.0f;
    if (tid < NWORK)
        xv = __ldg(xin + (size_t)blockIdx.x * NWORK + tid);

    // Phase 1: zero the tile (float4 stores, conflict-free).
    float4 z4 = make_float4(0.f, 0.f, 0.f, 0.f);
    float4* t4 = reinterpret_cast<float4*>(tile);
#pragma unroll
    for (int i = tid; i < TILE_VEC4; i += THREADS)
        t4[i] = z4;
    __syncthreads();

    // Phase 2: 192 workers, one per (point, dim).
    if (tid < NWORK) {
        const int p = tid / 3;
        const int d = tid - p * 3;

        float xs = fminf(fmaxf((xv + 1.0f) * SCALE, 0.0f), CLAMP_HI);
        float fi = floorf(xs);
        int  idx = (int)fi;
        float u  = xs - fi;
        float u2 = u * u;
        float u3 = u2 * u;
        float om = 1.0f - u;
        float c0 = om * om * om * (1.0f / 6.0f);
        float c1 = (3.0f * u3 - 6.0f * u2 + 4.0f) * (1.0f / 6.0f);
        float c2 = (-3.0f * u3 + 3.0f * u2 + 3.0f * u + 1.0f) * (1.0f / 6.0f);
        float c3 = u3 * (1.0f / 6.0f);

        float* dst = tile + p * 195 + d * 65;
        dst[0]       = xv;
        dst[1 + idx] = c0;
        dst[2 + idx] = c1;
        dst[3 + idx] = c2;
        dst[4 + idx] = c3;
    }
    __syncthreads();

    // Phase 3: four bulk-async (TMA) stores, one commit group.
    if (tid == 0) {
        asm volatile("fence.proxy.async.shared::cta;" ::: "memory");
        float* gdst = out + (size_t)blockIdx.x * TILE_FLOATS;
        uint32_t src = smem_u32(tile);
#pragma unroll
        for (int q = 0; q < 4; ++q) {
            asm volatile(
                "cp.async.bulk.global.shared::cta.bulk_group [%0], [%1], %2;"
                :: "l"(gdst + q * QTR_FLOATS), "r"(src + q * QTR_BYTES),
                   "n"(QTR_BYTES) : "memory");
        }
        asm volatile("cp.async.bulk.commit_group;" ::: "memory");
        // smem dies at block exit; bulk reads must finish first.
        asm volatile("cp.async.bulk.wait_group 0;" ::: "memory");
    }
}

extern "C" void kernel_launch(void* const* d_in, const int* in_sizes, int n_in,
                              void* d_out, int out_size)
{
    const float* x = (const float*)d_in[0];
    float* out = (float*)d_out;

    int n_points = out_size / 195;
    int blocks   = n_points / PTS_PER_BLK;   // 15625 for N = 1e6
    bspline_enc_kernel<<<blocks, THREADS>>>(x, out);
}